// round 1
// baseline (speedup 1.0000x reference)
#include <cuda_runtime.h>

#define BB 8192
#define HH 100
#define TT 512
#define NOPSN 5
#define ZW 400      // 4*H
#define JW 416      // padded z width (13 * 32)
#define RPB 56      // rows per block
#define RPW 7       // rows per warp
#define NWARP 8
#define NTHREADS 256

// Scratch (static device allocations are allowed)
__device__ float g_xW0[(size_t)BB * ZW];   // x0 @ W_x   [B,400]
__device__ float g_embW[6 * JW];           // emb @ W_x  [6,416] (cols >=400 zero)

__device__ __forceinline__ float fsig(float x) {
    return __fdividef(1.f, 1.f + __expf(-x));
}
__device__ __forceinline__ float ftanh_(float x) {
    float e = __expf(2.f * x);
    return 1.f - __fdividef(2.f, e + 1.f);   // saturates correctly at +/-1
}

__global__ void embW_kernel(const float* __restrict__ emb, const float* __restrict__ Wx) {
    int j = threadIdx.x;
    if (j >= JW) return;
    for (int e = 0; e < 6; ++e) {
        float acc = 0.f;
        if (j < ZW) {
            #pragma unroll 4
            for (int k = 0; k < HH; ++k)
                acc = fmaf(emb[e * HH + k], Wx[k * ZW + j], acc);
        }
        g_embW[e * JW + j] = acc;
    }
}

__global__ void xw0_kernel(const float* __restrict__ x0, const float* __restrict__ Wx) {
    __shared__ float xs[HH];
    int b = blockIdx.x;
    for (int i = threadIdx.x; i < HH; i += blockDim.x) xs[i] = x0[b * HH + i];
    __syncthreads();
    for (int j = threadIdx.x; j < ZW; j += blockDim.x) {
        float acc = 0.f;
        #pragma unroll 4
        for (int k = 0; k < HH; ++k) acc = fmaf(xs[k], Wx[k * ZW + j], acc);
        g_xW0[(size_t)b * ZW + j] = acc;
    }
}

__global__ void __launch_bounds__(NTHREADS, 1)
rnn_main(const float* __restrict__ Wh, const float* __restrict__ Wops,
         const float* __restrict__ u, float* __restrict__ out)
{
    extern __shared__ float sm[];
    float* sWh  = sm;                      // [100][416]
    float* sEmb = sWh + HH * JW;           // [6][416]
    float* sH   = sEmb + 6 * JW;           // [56][100]
    float* sZ   = sH + RPB * HH;           // [8][416] per-warp z scratch

    const int tid = threadIdx.x, wid = tid >> 5, lane = tid & 31;

    for (int i = tid; i < HH * JW; i += NTHREADS) {
        int k = i / JW, j = i - k * JW;
        sWh[i] = (j < ZW) ? Wh[k * ZW + j] : 0.f;
    }
    for (int i = tid; i < 6 * JW; i += NTHREADS) sEmb[i] = g_embW[i];
    for (int i = tid; i < RPB * HH; i += NTHREADS) sH[i] = 0.f;
    __syncthreads();

    const int rowBlock = blockIdx.x * RPB;
    const int lrow0 = wid * RPW;

    float cS[2][4][4];
    #pragma unroll
    for (int a = 0; a < 2; ++a)
        #pragma unroll
        for (int r = 0; r < 4; ++r)
            #pragma unroll
            for (int s = 0; s < 4; ++s) cS[a][r][s] = 0.f;

    float wopsr[4][NOPSN];
    #pragma unroll
    for (int s = 0; s < 4; ++s) {
        int unit = lane + 32 * s;
        #pragma unroll
        for (int n = 0; n < NOPSN; ++n)
            wopsr[s][n] = (unit < HH) ? Wops[unit * NOPSN + n] : 0.f;
    }

    float accLP[2] = {0.f, 0.f}, accENT[2] = {0.f, 0.f};
    int opReg[2] = {0, 0};

    for (int t = 0; t < TT; ++t) {
        #pragma unroll
        for (int ch = 0; ch < 2; ++ch) {
            const int CNT = (ch == 0) ? 4 : 3;
            const int lr = lrow0 + ch * 4;
            const int gb = rowBlock + lr;

            // prefetch gumbel inputs for this chunk (lanes 0..CNT*5-1)
            float ureg = 0.f;
            if (lane < CNT * NOPSN) {
                int r = lane / NOPSN, n = lane - r * NOPSN;
                int b = gb + r;
                if (b < BB) ureg = u[((size_t)t * BB + b) * NOPSN + n];
            }

            float z0[13], z1[13], z2[13], z3[13];
            if (t == 0) {
                #pragma unroll
                for (int s = 0; s < 13; ++s) {
                    int j = lane + 32 * s;
                    bool jc = (j < ZW);
                    z0[s] = (jc && 0 < CNT && gb + 0 < BB) ? g_xW0[(size_t)(gb + 0) * ZW + j] : 0.f;
                    z1[s] = (jc && 1 < CNT && gb + 1 < BB) ? g_xW0[(size_t)(gb + 1) * ZW + j] : 0.f;
                    z2[s] = (jc && 2 < CNT && gb + 2 < BB) ? g_xW0[(size_t)(gb + 2) * ZW + j] : 0.f;
                    z3[s] = (jc && 3 < CNT && gb + 3 < BB) ? g_xW0[(size_t)(gb + 3) * ZW + j] : 0.f;
                }
            } else {
                int o0 = __shfl_sync(0xffffffffu, opReg[ch], 0);
                int o1 = __shfl_sync(0xffffffffu, opReg[ch], 1);
                int o2 = __shfl_sync(0xffffffffu, opReg[ch], 2);
                int o3 = __shfl_sync(0xffffffffu, opReg[ch], 3);
                const float* e0 = sEmb + o0 * JW;
                const float* e1 = sEmb + o1 * JW;
                const float* e2 = sEmb + o2 * JW;
                const float* e3 = sEmb + o3 * JW;
                #pragma unroll
                for (int s = 0; s < 13; ++s) {
                    int j = lane + 32 * s;
                    z0[s] = e0[j]; z1[s] = e1[j]; z2[s] = e2[j]; z3[s] = e3[j];
                }
            }

            // h @ W_h mainloop (FMA-bound; W value reused across 4 rows)
            const int R0 = lr, R1 = lr + 1, R2 = lr + 2;
            const int R3 = (lr + 3 < RPB) ? (lr + 3) : (RPB - 1);
            #pragma unroll 2
            for (int k = 0; k < HH; ++k) {
                float h0 = sH[R0 * HH + k];
                float h1 = sH[R1 * HH + k];
                float h2 = sH[R2 * HH + k];
                float h3 = sH[R3 * HH + k];
                const float* wrow = sWh + k * JW + lane;
                #pragma unroll
                for (int s = 0; s < 13; ++s) {
                    float w = wrow[32 * s];
                    z0[s] = fmaf(h0, w, z0[s]);
                    z1[s] = fmaf(h1, w, z1[s]);
                    z2[s] = fmaf(h2, w, z2[s]);
                    z3[s] = fmaf(h3, w, z3[s]);
                }
            }

            float sums[5] = {0.f, 0.f, 0.f, 0.f, 0.f};

            auto gateStage = [&](float (&zz)[13], const int r, float (&cRow)[4]) {
                float* zb = sZ + wid * JW;
                #pragma unroll
                for (int s = 0; s < 13; ++s) zb[lane + 32 * s] = zz[s];
                __syncwarp();
                float pl[5] = {0.f, 0.f, 0.f, 0.f, 0.f};
                #pragma unroll
                for (int s = 0; s < 4; ++s) {
                    int unit = lane + 32 * s;
                    if (unit < HH) {
                        float zi = zb[unit];
                        float zf = zb[HH + unit];
                        float zc = zb[2 * HH + unit];
                        float zo = zb[3 * HH + unit];
                        float cn = fsig(zf) * cRow[s] + fsig(zi) * ftanh_(zc);
                        cRow[s] = cn;
                        float hn = fsig(zo) * ftanh_(cn);
                        sH[(lr + r) * HH + unit] = hn;
                        #pragma unroll
                        for (int n = 0; n < 5; ++n) pl[n] = fmaf(hn, wopsr[s][n], pl[n]);
                    }
                }
                __syncwarp();
                #pragma unroll
                for (int off = 16; off; off >>= 1) {
                    #pragma unroll
                    for (int n = 0; n < 5; ++n)
                        pl[n] += __shfl_xor_sync(0xffffffffu, pl[n], off);
                }
                if (lane == r) {
                    #pragma unroll
                    for (int n = 0; n < 5; ++n) sums[n] = pl[n];
                }
            };

            gateStage(z0, 0, cS[ch][0]);
            gateStage(z1, 1, cS[ch][1]);
            gateStage(z2, 2, cS[ch][2]);
            if (CNT > 3) gateStage(z3, 3, cS[ch][3]);

            // distribute u values to the per-row scalar lanes (convergent)
            float un[5];
            #pragma unroll
            for (int n = 0; n < 5; ++n)
                un[n] = __shfl_sync(0xffffffffu, ureg, lane * 5 + n);

            if (lane < CNT) {
                int b = gb + lane;
                if (b < BB) {
                    float lg[5];
                    #pragma unroll
                    for (int n = 0; n < 5; ++n) lg[n] = 1.5f * tanhf(sums[n]);
                    int op = 0;
                    float best = 0.f, m = lg[0], lgsel = lg[0];
                    #pragma unroll
                    for (int n = 0; n < 5; ++n) {
                        float gum = -logf(-logf(un[n] + 1e-9f) + 1e-9f);
                        float v = lg[n] + gum;
                        if (n == 0) { best = v; }
                        else if (v > best) { best = v; op = n; lgsel = lg[n]; }
                        if (lg[n] > m) m = lg[n];
                    }
                    float ssum = 0.f;
                    #pragma unroll
                    for (int n = 0; n < 5; ++n) ssum += expf(lg[n] - m);
                    float lse = m + logf(ssum);
                    float cur = lse - lgsel;          // -log_softmax(logits)[op]
                    float ent = cur * expf(-cur);
                    accLP[ch] += cur;
                    accENT[ch] += ent;
                    opReg[ch] = op;
                    out[2 * (size_t)BB + (size_t)t * BB + b] = (float)op;
                }
            }
            __syncwarp();
        }
    }

    #pragma unroll
    for (int ch = 0; ch < 2; ++ch) {
        const int CNT = (ch == 0) ? 4 : 3;
        if (lane < CNT) {
            int b = rowBlock + lrow0 + ch * 4 + lane;
            if (b < BB) {
                out[b] = accLP[ch];
                out[BB + b] = accENT[ch];
            }
        }
    }
}

extern "C" void kernel_launch(void* const* d_in, const int* in_sizes, int n_in,
                              void* d_out, int out_size) {
    const float* x0  = (const float*)d_in[0];
    const float* Wx  = (const float*)d_in[1];
    const float* Wh  = (const float*)d_in[2];
    const float* Wop = (const float*)d_in[3];
    const float* emb = (const float*)d_in[4];
    const float* u   = (const float*)d_in[5];
    float* out = (float*)d_out;

    size_t smem = (size_t)(HH * JW + 6 * JW + RPB * HH + NWARP * JW) * sizeof(float);
    cudaFuncSetAttribute(rnn_main, cudaFuncAttributeMaxDynamicSharedMemorySize, (int)smem);

    embW_kernel<<<1, JW>>>(emb, Wx);
    xw0_kernel<<<BB, 128>>>(x0, Wx);
    int grid = (BB + RPB - 1) / RPB;   // 147 blocks, one wave on 148 SMs
    rnn_main<<<grid, NTHREADS, smem>>>(Wh, Wop, u, out);
}

// round 2
// speedup vs baseline: 1.5175x; 1.5175x over previous
#include <cuda_runtime.h>

#define BB 8192
#define HH 100
#define TT 512
#define NOPSN 5
#define ZW 400      // 4*H
#define EW 448      // padded width for emb@Wx rows (7*64)
#define RPW 7       // rows per warp
#define NWARP 8
#define RPB 56      // rows per block
#define NTHREADS 256

typedef unsigned long long u64t;

// Scratch (static device allocations are allowed)
__device__ float g_xW0[(size_t)BB * ZW];   // x0 @ W_x   [B,400]
__device__ float g_embW[6 * EW];           // emb @ W_x  [6,448] (cols >=400 zero)

__device__ __forceinline__ float fsig(float x) {
    return __fdividef(1.f, 1.f + __expf(-x));
}
__device__ __forceinline__ float ftanh_(float x) {
    float e = __expf(2.f * x);
    return 1.f - __fdividef(2.f, e + 1.f);   // saturates correctly at +/-1
}
// packed fp32x2 FMA: d = a*b + c (elementwise on the two f32 halves)
__device__ __forceinline__ u64t ffma2(u64t a, u64t b, u64t c) {
    u64t d;
    asm("fma.rn.f32x2 %0, %1, %2, %3;" : "=l"(d) : "l"(a), "l"(b), "l"(c));
    return d;
}
__device__ __forceinline__ u64t pack2(float x) {
    unsigned int xi = __float_as_uint(x);
    u64t d;
    asm("mov.b64 %0, {%1, %2};" : "=l"(d) : "r"(xi), "r"(xi));
    return d;
}

__global__ void embW_kernel(const float* __restrict__ emb, const float* __restrict__ Wx) {
    int j = threadIdx.x;
    if (j >= EW) return;
    for (int e = 0; e < 6; ++e) {
        float acc = 0.f;
        if (j < ZW) {
            #pragma unroll 4
            for (int k = 0; k < HH; ++k)
                acc = fmaf(emb[e * HH + k], Wx[k * ZW + j], acc);
        }
        g_embW[e * EW + j] = acc;
    }
}

__global__ void xw0_kernel(const float* __restrict__ x0, const float* __restrict__ Wx) {
    __shared__ float xs[HH];
    int b = blockIdx.x;
    for (int i = threadIdx.x; i < HH; i += blockDim.x) xs[i] = x0[b * HH + i];
    __syncthreads();
    for (int j = threadIdx.x; j < ZW; j += blockDim.x) {
        float acc = 0.f;
        #pragma unroll 4
        for (int k = 0; k < HH; ++k) acc = fmaf(xs[k], Wx[k * ZW + j], acc);
        g_xW0[(size_t)b * ZW + j] = acc;
    }
}

__global__ void __launch_bounds__(NTHREADS, 1)
rnn_main(const float* __restrict__ Wh, const float* __restrict__ Wops,
         const float* __restrict__ u, float* __restrict__ out)
{
    extern __shared__ float sm[];
    float* sWh  = sm;                      // [100][400] unpadded
    float* sEmb = sWh + HH * ZW;           // [6][448]
    float* sH   = sEmb + 6 * EW;           // [56][100]
    float* sZ   = sH + RPB * HH;           // [8][400] per-warp z scratch

    const int tid = threadIdx.x, wid = tid >> 5, lane = tid & 31;

    for (int i = tid; i < HH * ZW; i += NTHREADS) sWh[i] = Wh[i];
    for (int i = tid; i < 6 * EW; i += NTHREADS)  sEmb[i] = g_embW[i];
    for (int i = tid; i < RPB * HH; i += NTHREADS) sH[i] = 0.f;
    __syncthreads();

    const int rowBlock = blockIdx.x * RPB;
    const int lrow0 = wid * RPW;           // first row (in block) for this warp
    const int gb0 = rowBlock + lrow0;      // first global row for this warp

    float cS[RPW][4];
    #pragma unroll
    for (int r = 0; r < RPW; ++r)
        #pragma unroll
        for (int s = 0; s < 4; ++s) cS[r][s] = 0.f;

    float wopsr[4][NOPSN];
    #pragma unroll
    for (int s = 0; s < 4; ++s) {
        int unit = lane + 32 * s;
        #pragma unroll
        for (int n = 0; n < NOPSN; ++n)
            wopsr[s][n] = (unit < HH) ? Wops[unit * NOPSN + n] : 0.f;
    }

    // per-lane scalars: lane r (<7) owns row gb0+r
    float accLP = 0.f, accENT = 0.f;
    int opReg = 0;

    for (int t = 0; t < TT; ++t) {
        // ---- prefetch gumbel inputs for this warp's 7 rows (35 contiguous floats) ----
        float un[NOPSN] = {0.f, 0.f, 0.f, 0.f, 0.f};
        {
            int b = gb0 + lane;
            if (lane < RPW && b < BB) {
                const float* up = u + ((size_t)t * BB + b) * NOPSN;
                #pragma unroll
                for (int n = 0; n < NOPSN; ++n) un[n] = up[n];
            }
        }

        // ---- init z accumulators (pairs: lane handles j = 2*lane + 64*s) ----
        u64t z[RPW][7];
        if (t == 0) {
            #pragma unroll
            for (int r = 0; r < RPW; ++r) {
                int bb = gb0 + r; if (bb >= BB) bb = BB - 1;
                const float* xp = g_xW0 + (size_t)bb * ZW;
                #pragma unroll
                for (int s = 0; s < 7; ++s) {
                    int j = 2 * lane + 64 * s;
                    z[r][s] = (j < ZW) ? *(const u64t*)(xp + j) : 0ull;
                }
            }
        } else {
            #pragma unroll
            for (int r = 0; r < RPW; ++r) {
                int orr = __shfl_sync(0xffffffffu, opReg, r);
                const float* ep = sEmb + orr * EW;
                #pragma unroll
                for (int s = 0; s < 7; ++s)
                    z[r][s] = *(const u64t*)(ep + 2 * lane + 64 * s);
            }
        }

        // ---- h @ W_h mainloop: 7 rows share every weight load, packed FMA ----
        #pragma unroll 2
        for (int k = 0; k < HH; ++k) {
            u64t hp[RPW];
            #pragma unroll
            for (int r = 0; r < RPW; ++r)
                hp[r] = pack2(sH[(lrow0 + r) * HH + k]);
            const float* wrow = sWh + k * ZW + 2 * lane;
            #pragma unroll
            for (int s = 0; s < 7; ++s) {
                u64t w = *(const u64t*)(wrow + 64 * s);  // may over-read into sEmb pad; discarded lanes
                #pragma unroll
                for (int r = 0; r < RPW; ++r)
                    z[r][s] = ffma2(hp[r], w, z[r][s]);
            }
        }

        // ---- gates + logits per row ----
        float sums[NOPSN] = {0.f, 0.f, 0.f, 0.f, 0.f};
        float* zb = sZ + wid * ZW;

        #pragma unroll
        for (int r = 0; r < RPW; ++r) {
            #pragma unroll
            for (int s = 0; s < 7; ++s) {
                int j = 2 * lane + 64 * s;
                if (s < 6 || lane < 8) *(u64t*)(zb + j) = z[r][s];
            }
            __syncwarp();
            float pl[NOPSN] = {0.f, 0.f, 0.f, 0.f, 0.f};
            #pragma unroll
            for (int s2 = 0; s2 < 4; ++s2) {
                int unit = lane + 32 * s2;
                if (unit < HH) {
                    float zi = zb[unit];
                    float zf = zb[HH + unit];
                    float zc = zb[2 * HH + unit];
                    float zo = zb[3 * HH + unit];
                    float cn = fsig(zf) * cS[r][s2] + fsig(zi) * ftanh_(zc);
                    cS[r][s2] = cn;
                    float hn = fsig(zo) * ftanh_(cn);
                    sH[(lrow0 + r) * HH + unit] = hn;
                    #pragma unroll
                    for (int n = 0; n < NOPSN; ++n)
                        pl[n] = fmaf(hn, wopsr[s2][n], pl[n]);
                }
            }
            __syncwarp();
            #pragma unroll
            for (int off = 16; off; off >>= 1) {
                #pragma unroll
                for (int n = 0; n < NOPSN; ++n)
                    pl[n] += __shfl_xor_sync(0xffffffffu, pl[n], off);
            }
            if (lane == r) {
                #pragma unroll
                for (int n = 0; n < NOPSN; ++n) sums[n] = pl[n];
            }
        }

        // ---- sampling / log-softmax epilogue (lanes 0..6 = rows) ----
        if (lane < RPW) {
            int b = gb0 + lane;
            if (b < BB) {
                float lg[NOPSN];
                #pragma unroll
                for (int n = 0; n < NOPSN; ++n) lg[n] = 1.5f * tanhf(sums[n]);
                int op = 0;
                float best = 0.f, m = lg[0], lgsel = lg[0];
                #pragma unroll
                for (int n = 0; n < NOPSN; ++n) {
                    float gum = -logf(-logf(un[n] + 1e-9f) + 1e-9f);
                    float v = lg[n] + gum;
                    if (n == 0) { best = v; }
                    else if (v > best) { best = v; op = n; lgsel = lg[n]; }
                    if (lg[n] > m) m = lg[n];
                }
                float ssum = 0.f;
                #pragma unroll
                for (int n = 0; n < NOPSN; ++n) ssum += expf(lg[n] - m);
                float lse = m + logf(ssum);
                float cur = lse - lgsel;          // -log_softmax(logits)[op]
                float ent = cur * expf(-cur);
                accLP += cur;
                accENT += ent;
                opReg = op;
                out[2 * (size_t)BB + (size_t)t * BB + b] = (float)op;
            }
        }
        __syncwarp();
    }

    if (lane < RPW) {
        int b = gb0 + lane;
        if (b < BB) {
            out[b] = accLP;
            out[BB + b] = accENT;
        }
    }
}

extern "C" void kernel_launch(void* const* d_in, const int* in_sizes, int n_in,
                              void* d_out, int out_size) {
    const float* x0  = (const float*)d_in[0];
    const float* Wx  = (const float*)d_in[1];
    const float* Wh  = (const float*)d_in[2];
    const float* Wop = (const float*)d_in[3];
    const float* emb = (const float*)d_in[4];
    const float* u   = (const float*)d_in[5];
    float* out = (float*)d_out;

    size_t smem = (size_t)(HH * ZW + 6 * EW + RPB * HH + NWARP * ZW) * sizeof(float);
    cudaFuncSetAttribute(rnn_main, cudaFuncAttributeMaxDynamicSharedMemorySize, (int)smem);

    embW_kernel<<<1, EW>>>(emb, Wx);
    xw0_kernel<<<BB, 128>>>(x0, Wx);
    int grid = (BB + RPB - 1) / RPB;   // 147 blocks, one wave on 148 SMs
    rnn_main<<<grid, NTHREADS, smem>>>(Wh, Wop, u, out);
}